// round 1
// baseline (speedup 1.0000x reference)
#include <cuda_runtime.h>
#include <math.h>

#define TPB 128
#define TILE 512
#define PBATCH 2
#define NSCALES 4

// Scratch for per-point curvature vectors across all scales & batches.
// Total points = 2*(8192+4096+2048+1024) = 30720  -> pad to 40000.
__device__ float g_cv2[40000 * 3];
__device__ float g_cvw[40000 * 3];

__constant__ float c_alpha_pwc[4] = {0.02f, 0.04f, 0.08f, 0.16f};

struct PwcParams {
    const float* pc1[NSCALES];
    const float* pc2[NSCALES];
    const float* flow[NSCALES];
    int N[NSCALES];
    int off[NSCALES];   // point offset into scratch per scale
};

// Block-wide sum + single atomicAdd into the scalar output.
__device__ __forceinline__ void block_add(float v, float* out) {
    #pragma unroll
    for (int o = 16; o; o >>= 1) v += __shfl_down_sync(0xffffffffu, v, o);
    __shared__ float red[TPB / 32];
    if ((threadIdx.x & 31) == 0) red[threadIdx.x >> 5] = v;
    __syncthreads();
    if (threadIdx.x == 0) {
        float s = 0.f;
        #pragma unroll
        for (int w = 0; w < TPB / 32; w++) s += red[w];
        atomicAdd(out, s);
    }
}

// Brute-force K-nearest scan of query q against M reference points (SoA: x|y|z planes).
// WARPREF: refs are ra + rb (warp = p1 + flow), built during the tile load.
// All threads of the block must call this (barriers inside); inactive threads
// pass active=false and just help load tiles.
template <int K, bool WARPREF>
__device__ __forceinline__ void knn_scan(
    const float* __restrict__ ra, const float* __restrict__ rb, int M,
    bool active, float qx, float qy, float qz,
    float* dl, int* il)
{
    __shared__ float sx[TILE], sy[TILE], sz[TILE];
    #pragma unroll
    for (int k = 0; k < K; k++) { dl[k] = 3.4e38f; il[k] = 0; }

    for (int base = 0; base < M; base += TILE) {
        int cnt = min(TILE, M - base);
        __syncthreads();
        for (int i = threadIdx.x; i < cnt; i += TPB) {
            float x = ra[base + i];
            float y = ra[M + base + i];
            float z = ra[2 * M + base + i];
            if (WARPREF) {
                x += rb[base + i];
                y += rb[M + base + i];
                z += rb[2 * M + base + i];
            }
            sx[i] = x; sy[i] = y; sz[i] = z;
        }
        __syncthreads();
        if (active) {
            #pragma unroll 4
            for (int j = 0; j < cnt; j++) {
                float dx = qx - sx[j];
                float dy = qy - sy[j];
                float dz = qz - sz[j];
                float d = fmaf(dx, dx, fmaf(dy, dy, dz * dz));
                if (d < dl[K - 1]) {
                    dl[K - 1] = d; il[K - 1] = base + j;
                    #pragma unroll
                    for (int k = K - 1; k > 0; k--) {
                        if (dl[k] < dl[k - 1]) {   // strict: preserves low-index tie-break
                            float td = dl[k]; dl[k] = dl[k - 1]; dl[k - 1] = td;
                            int ti = il[k]; il[k] = il[k - 1]; il[k - 1] = ti;
                        }
                    }
                }
            }
        }
    }
}

// phase1: grid.y = 12 tasks (type = y>>2 in {0:cv2-knn, 1:cvw+smooth-knn, 2:dist2-min},
//         scale = y&3), grid.z = batch. Independent of phase2's inputs.
__global__ __launch_bounds__(TPB) void pwc_phase1(PwcParams P, float* __restrict__ out) {
    int type  = blockIdx.y >> 2;
    int scale = blockIdx.y & 3;
    int N = P.N[scale];
    if ((int)blockIdx.x * TPB >= N) return;
    int b = blockIdx.z;
    int n = blockIdx.x * TPB + threadIdx.x;
    bool active = n < N;
    int nn = active ? n : 0;

    const float* p1 = P.pc1[scale]  + b * 3 * N;
    const float* p2 = P.pc2[scale]  + b * 3 * N;
    const float* fl = P.flow[scale] + b * 3 * N;
    float a = c_alpha_pwc[scale];
    float contrib = 0.f;

    if (type == 0) {
        // knn10(p2,p2) -> cv2
        float qx = p2[nn], qy = p2[N + nn], qz = p2[2 * N + nn];
        float dl[10]; int il[10];
        knn_scan<10, false>(p2, nullptr, N, active, qx, qy, qz, dl, il);
        if (active) {
            float sxx = 0.f, syy = 0.f, szz = 0.f;
            #pragma unroll
            for (int k = 0; k < 10; k++) {
                int id = il[k];
                sxx += __ldg(p2 + id);
                syy += __ldg(p2 + N + id);
                szz += __ldg(p2 + 2 * N + id);
            }
            int o = (P.off[scale] + b * N + n) * 3;
            const float inv9 = 1.f / 9.f;
            g_cv2[o + 0] = (sxx - 10.f * qx) * inv9;
            g_cv2[o + 1] = (syy - 10.f * qy) * inv9;
            g_cv2[o + 2] = (szz - 10.f * qz) * inv9;
        }
    } else if (type == 1) {
        // knn10(p1,p1) -> cvw (on warp) + smoothness (on flow, first 9 nbrs)
        float qx = p1[nn], qy = p1[N + nn], qz = p1[2 * N + nn];
        float dl[10]; int il[10];
        knn_scan<10, false>(p1, nullptr, N, active, qx, qy, qz, dl, il);
        if (active) {
            float fx = fl[nn], fy = fl[N + nn], fz = fl[2 * N + nn];
            float wqx = qx + fx, wqy = qy + fy, wqz = qz + fz;
            float swx = 0.f, swy = 0.f, swz = 0.f, sm = 0.f;
            #pragma unroll
            for (int k = 0; k < 10; k++) {
                int id = il[k];
                float gx = __ldg(fl + id), gy = __ldg(fl + N + id), gz = __ldg(fl + 2 * N + id);
                float px = __ldg(p1 + id), py = __ldg(p1 + N + id), pz = __ldg(p1 + 2 * N + id);
                swx += px + gx; swy += py + gy; swz += pz + gz;
                if (k < 9) {
                    float dx = gx - fx, dy = gy - fy, dz = gz - fz;
                    sm += sqrtf(fmaf(dx, dx, fmaf(dy, dy, dz * dz)));
                }
            }
            int o = (P.off[scale] + b * N + n) * 3;
            const float inv9 = 1.f / 9.f;
            g_cvw[o + 0] = (swx - 10.f * wqx) * inv9;
            g_cvw[o + 1] = (swy - 10.f * wqy) * inv9;
            g_cvw[o + 2] = (swz - 10.f * wqz) * inv9;
            contrib = a * (1.f / PBATCH) * sm * 0.125f;   // SMOOTH_W = 1, /8
        }
    } else {
        // dist2[m] = min_n d12 : query p2 point, refs = warp (p1+flow)
        float qx = p2[nn], qy = p2[N + nn], qz = p2[2 * N + nn];
        float dl[1]; int il[1];
        knn_scan<1, true>(p1, fl, N, active, qx, qy, qz, dl, il);
        if (active) contrib = a * (1.f / PBATCH) * dl[0];  // CHAMFER_W = 1
    }
    block_add(contrib, out);
}

// phase2: knn5(warp, p2) -> chamfer dist1 + inverse-distance interpolated
// curvature loss. Depends on g_cv2 / g_cvw from phase1.
__global__ __launch_bounds__(TPB) void pwc_phase2(PwcParams P, float* __restrict__ out) {
    int scale = blockIdx.y;
    int N = P.N[scale];
    if ((int)blockIdx.x * TPB >= N) return;
    int b = blockIdx.z;
    int n = blockIdx.x * TPB + threadIdx.x;
    bool active = n < N;
    int nn = active ? n : 0;

    const float* p1 = P.pc1[scale]  + b * 3 * N;
    const float* p2 = P.pc2[scale]  + b * 3 * N;
    const float* fl = P.flow[scale] + b * 3 * N;

    float qx = p1[nn] + fl[nn];
    float qy = p1[N + nn] + fl[N + nn];
    float qz = p1[2 * N + nn] + fl[2 * N + nn];

    float dl[5]; int il[5];
    knn_scan<5, false>(p2, nullptr, N, active, qx, qy, qz, dl, il);

    float contrib = 0.f;
    if (active) {
        float a = c_alpha_pwc[scale];
        float w[5], wsum = 0.f;
        #pragma unroll
        for (int k = 0; k < 5; k++) { w[k] = 1.0f / (dl[k] + 1e-8f); wsum += w[k]; }
        float invws = 1.0f / wsum;
        float ix = 0.f, iy = 0.f, iz = 0.f;
        #pragma unroll
        for (int k = 0; k < 5; k++) {
            int o = (P.off[scale] + b * N + il[k]) * 3;
            float ww = w[k] * invws;
            ix = fmaf(ww, g_cv2[o + 0], ix);
            iy = fmaf(ww, g_cv2[o + 1], iy);
            iz = fmaf(ww, g_cv2[o + 2], iz);
        }
        int oc = (P.off[scale] + b * N + n) * 3;
        float dx = ix - g_cvw[oc + 0];
        float dy = iy - g_cvw[oc + 1];
        float dz = iz - g_cvw[oc + 2];
        float curv = fmaf(dx, dx, fmaf(dy, dy, dz * dz));
        contrib = a * (1.f / PBATCH) * (dl[0] + 0.3f * curv);  // CHAMFER_W=1, CURVATURE_W=0.3
    }
    block_add(contrib, out);
}

__global__ void pwc_zero(float* out) { if (threadIdx.x == 0) out[0] = 0.f; }

extern "C" void kernel_launch(void* const* d_in, const int* in_sizes, int n_in,
                              void* d_out, int out_size) {
    PwcParams P;
    int off = 0;
    int maxN = 0;
    for (int s = 0; s < NSCALES; s++) {
        P.pc1[s]  = (const float*)d_in[s];
        P.pc2[s]  = (const float*)d_in[4 + s];
        P.flow[s] = (const float*)d_in[8 + s];
        int N = in_sizes[s] / (3 * PBATCH);
        P.N[s] = N;
        P.off[s] = off;
        off += PBATCH * N;
        if (N > maxN) maxN = N;
    }
    float* out = (float*)d_out;
    pwc_zero<<<1, 32>>>(out);

    int blocksX = (maxN + TPB - 1) / TPB;
    dim3 g1(blocksX, 12, PBATCH);
    pwc_phase1<<<g1, TPB>>>(P, out);
    dim3 g2(blocksX, 4, PBATCH);
    pwc_phase2<<<g2, TPB>>>(P, out);
}

// round 2
// speedup vs baseline: 1.5247x; 1.5247x over previous
#include <cuda_runtime.h>
#include <math.h>

#define TPB 128
#define TILE 1024
#define PBATCH 2
#define NSCALES 4

// Scratch: total points = 2*(8192+4096+2048+1024) = 30720 -> pad 40000.
__device__ float g_cv2[40000 * 3];
__device__ float g_cvw[40000 * 3];
__device__ float g_kd[40000 * 5];   // knn5 true distances (warp -> p2)
__device__ int   g_ki[40000 * 5];   // knn5 indices

__constant__ float c_alpha_pwc[4] = {0.02f, 0.04f, 0.08f, 0.16f};

struct PwcParams {
    const float* pc1[NSCALES];
    const float* pc2[NSCALES];
    const float* flow[NSCALES];
    int N[NSCALES];
    int off[NSCALES];
};

__device__ __forceinline__ void block_add(float v, float* out) {
    #pragma unroll
    for (int o = 16; o; o >>= 1) v += __shfl_down_sync(0xffffffffu, v, o);
    __shared__ float red[TPB / 32];
    if ((threadIdx.x & 31) == 0) red[threadIdx.x >> 5] = v;
    __syncthreads();
    if (threadIdx.x == 0) {
        float s = 0.f;
        #pragma unroll
        for (int w = 0; w < TPB / 32; w++) s += red[w];
        atomicAdd(out, s);
    }
}

// Brute-force K-nearest using the expanded distance form:
//   d' = |s|^2 - 2 q.s      (monotone in true d for fixed q; true d = d' + |q|^2)
// Tiles hold float4 (x, y, z, |s|^2). WARPREF: refs = ra + rb (p1 + flow).
// All block threads must call (barriers inside).
template <int K, bool WARPREF>
__device__ __forceinline__ void knn_scan(
    const float* __restrict__ ra, const float* __restrict__ rb, int M,
    bool active, float qx, float qy, float qz,
    float* dl, int* il)
{
    __shared__ float4 tile[TILE];
    const float nqx = -2.f * qx, nqy = -2.f * qy, nqz = -2.f * qz;
    #pragma unroll
    for (int k = 0; k < K; k++) { dl[k] = 3.4e38f; il[k] = 0; }

    for (int base = 0; base < M; base += TILE) {
        int cnt = min(TILE, M - base);
        __syncthreads();
        for (int i = threadIdx.x; i < cnt; i += TPB) {
            float x = ra[base + i];
            float y = ra[M + base + i];
            float z = ra[2 * M + base + i];
            if (WARPREF) {
                x += rb[base + i];
                y += rb[M + base + i];
                z += rb[2 * M + base + i];
            }
            tile[i] = make_float4(x, y, z, fmaf(x, x, fmaf(y, y, z * z)));
        }
        __syncthreads();
        if (active) {
            #pragma unroll 4
            for (int j = 0; j < cnt; j++) {
                float4 s = tile[j];
                float d = fmaf(nqx, s.x, fmaf(nqy, s.y, fmaf(nqz, s.z, s.w)));
                if (d < dl[K - 1]) {
                    dl[K - 1] = d; il[K - 1] = base + j;
                    #pragma unroll
                    for (int k = K - 1; k > 0; k--) {
                        if (dl[k] < dl[k - 1]) {   // strict: low-index tie-break
                            float td = dl[k]; dl[k] = dl[k - 1]; dl[k - 1] = td;
                            int ti = il[k]; il[k] = il[k - 1]; il[k - 1] = ti;
                        }
                    }
                }
            }
        }
    }
}

// phase1: grid.y = 16 tasks (type = y>>2, scale = y&3), grid.z = batch.
//   type0: knn10(p2,p2)  -> cv2
//   type1: knn10(p1,p1)  -> cvw + smoothness
//   type2: min over warp refs for each p2 query -> chamfer dist2
//   type3: knn5(warp,p2) -> chamfer dist1, store dl/il for phase2
__global__ __launch_bounds__(TPB) void pwc_phase1(PwcParams P, float* __restrict__ out) {
    int type  = blockIdx.y >> 2;
    int scale = blockIdx.y & 3;
    int N = P.N[scale];
    if ((int)blockIdx.x * TPB >= N) return;
    int b = blockIdx.z;
    int n = blockIdx.x * TPB + threadIdx.x;
    bool active = n < N;
    int nn = active ? n : 0;

    const float* p1 = P.pc1[scale]  + b * 3 * N;
    const float* p2 = P.pc2[scale]  + b * 3 * N;
    const float* fl = P.flow[scale] + b * 3 * N;
    float a = c_alpha_pwc[scale];
    float contrib = 0.f;

    if (type == 0) {
        float qx = p2[nn], qy = p2[N + nn], qz = p2[2 * N + nn];
        float dl[10]; int il[10];
        knn_scan<10, false>(p2, nullptr, N, active, qx, qy, qz, dl, il);
        if (active) {
            float sxx = 0.f, syy = 0.f, szz = 0.f;
            #pragma unroll
            for (int k = 0; k < 10; k++) {
                int id = il[k];
                sxx += __ldg(p2 + id);
                syy += __ldg(p2 + N + id);
                szz += __ldg(p2 + 2 * N + id);
            }
            int o = (P.off[scale] + b * N + n) * 3;
            const float inv9 = 1.f / 9.f;
            g_cv2[o + 0] = (sxx - 10.f * qx) * inv9;
            g_cv2[o + 1] = (syy - 10.f * qy) * inv9;
            g_cv2[o + 2] = (szz - 10.f * qz) * inv9;
        }
    } else if (type == 1) {
        float qx = p1[nn], qy = p1[N + nn], qz = p1[2 * N + nn];
        float dl[10]; int il[10];
        knn_scan<10, false>(p1, nullptr, N, active, qx, qy, qz, dl, il);
        if (active) {
            float fx = fl[nn], fy = fl[N + nn], fz = fl[2 * N + nn];
            float wqx = qx + fx, wqy = qy + fy, wqz = qz + fz;
            float swx = 0.f, swy = 0.f, swz = 0.f, sm = 0.f;
            #pragma unroll
            for (int k = 0; k < 10; k++) {
                int id = il[k];
                float gx = __ldg(fl + id), gy = __ldg(fl + N + id), gz = __ldg(fl + 2 * N + id);
                float px = __ldg(p1 + id), py = __ldg(p1 + N + id), pz = __ldg(p1 + 2 * N + id);
                swx += px + gx; swy += py + gy; swz += pz + gz;
                if (k < 9) {
                    float dx = gx - fx, dy = gy - fy, dz = gz - fz;
                    sm += sqrtf(fmaf(dx, dx, fmaf(dy, dy, dz * dz)));
                }
            }
            int o = (P.off[scale] + b * N + n) * 3;
            const float inv9 = 1.f / 9.f;
            g_cvw[o + 0] = (swx - 10.f * wqx) * inv9;
            g_cvw[o + 1] = (swy - 10.f * wqy) * inv9;
            g_cvw[o + 2] = (swz - 10.f * wqz) * inv9;
            contrib = a * (1.f / PBATCH) * sm * 0.125f;
        }
    } else if (type == 2) {
        float qx = p2[nn], qy = p2[N + nn], qz = p2[2 * N + nn];
        float dl[1]; int il[1];
        knn_scan<1, true>(p1, fl, N, active, qx, qy, qz, dl, il);
        if (active) {
            float qn = fmaf(qx, qx, fmaf(qy, qy, qz * qz));
            contrib = a * (1.f / PBATCH) * (dl[0] + qn);
        }
    } else {
        float qx = p1[nn] + fl[nn];
        float qy = p1[N + nn] + fl[N + nn];
        float qz = p1[2 * N + nn] + fl[2 * N + nn];
        float dl[5]; int il[5];
        knn_scan<5, false>(p2, nullptr, N, active, qx, qy, qz, dl, il);
        if (active) {
            float qn = fmaf(qx, qx, fmaf(qy, qy, qz * qz));
            int o = (P.off[scale] + b * N + n) * 5;
            #pragma unroll
            for (int k = 0; k < 5; k++) {
                g_kd[o + k] = dl[k] + qn;
                g_ki[o + k] = il[k];
            }
            contrib = a * (1.f / PBATCH) * (dl[0] + qn);
        }
    }
    block_add(contrib, out);
}

// phase2: tiny gather — inverse-distance interpolated curvature loss.
__global__ __launch_bounds__(TPB) void pwc_phase2(PwcParams P, float* __restrict__ out) {
    int scale = blockIdx.y;
    int N = P.N[scale];
    if ((int)blockIdx.x * TPB >= N) return;
    int b = blockIdx.z;
    int n = blockIdx.x * TPB + threadIdx.x;
    float contrib = 0.f;

    if (n < N) {
        int base = P.off[scale] + b * N;
        int o = (base + n) * 5;
        float w[5], wsum = 0.f; int il[5];
        #pragma unroll
        for (int k = 0; k < 5; k++) {
            w[k] = 1.0f / (g_kd[o + k] + 1e-8f);
            il[k] = g_ki[o + k];
            wsum += w[k];
        }
        float invws = 1.0f / wsum;
        float ix = 0.f, iy = 0.f, iz = 0.f;
        #pragma unroll
        for (int k = 0; k < 5; k++) {
            int oc = (base + il[k]) * 3;
            float ww = w[k] * invws;
            ix = fmaf(ww, g_cv2[oc + 0], ix);
            iy = fmaf(ww, g_cv2[oc + 1], iy);
            iz = fmaf(ww, g_cv2[oc + 2], iz);
        }
        int oc = (base + n) * 3;
        float dx = ix - g_cvw[oc + 0];
        float dy = iy - g_cvw[oc + 1];
        float dz = iz - g_cvw[oc + 2];
        float curv = fmaf(dx, dx, fmaf(dy, dy, dz * dz));
        contrib = c_alpha_pwc[scale] * (1.f / PBATCH) * 0.3f * curv;
    }
    block_add(contrib, out);
}

extern "C" void kernel_launch(void* const* d_in, const int* in_sizes, int n_in,
                              void* d_out, int out_size) {
    PwcParams P;
    int off = 0;
    int maxN = 0;
    for (int s = 0; s < NSCALES; s++) {
        P.pc1[s]  = (const float*)d_in[s];
        P.pc2[s]  = (const float*)d_in[4 + s];
        P.flow[s] = (const float*)d_in[8 + s];
        int N = in_sizes[s] / (3 * PBATCH);
        P.N[s] = N;
        P.off[s] = off;
        off += PBATCH * N;
        if (N > maxN) maxN = N;
    }
    float* out = (float*)d_out;
    cudaMemsetAsync(out, 0, sizeof(float));

    int blocksX = (maxN + TPB - 1) / TPB;
    dim3 g1(blocksX, 16, PBATCH);
    pwc_phase1<<<g1, TPB>>>(P, out);
    dim3 g2(blocksX, 4, PBATCH);
    pwc_phase2<<<g2, TPB>>>(P, out);
}